// round 1
// baseline (speedup 1.0000x reference)
#include <cuda_runtime.h>

// Problem constants
#define S_DIM 5
#define B_DIM 16
#define C_DIM 11
#define H_DIM 128
#define W_DIM 128
#define SLICE   (C_DIM * H_DIM * W_DIM)   // 180224 floats per (s,b)
#define SLICE4  (SLICE / 4)               // 45056 float4 per (s,b)
#define NSLICE  (S_DIM * B_DIM)           // 80
#define BLOCKS_PER_SLICE 16
#define THREADS 256
#define NCLASS 11
#define F_DIM 7
#define LBL (NCLASS * F_DIM)              // 77

// Deterministic two-stage reduction scratch (no cudaMalloc allowed)
__device__ float g_partial[NSLICE * BLOCKS_PER_SLICE];

__global__ void heat_partial_kernel(const float4* __restrict__ hp,
                                    const float4* __restrict__ hm) {
    const int p = blockIdx.y;  // slice = s*B + b
    const float4* __restrict__ a = hp + (size_t)p * SLICE4;
    const float4* __restrict__ b = hm + (size_t)p * SLICE4;

    float sum = 0.0f;
    // 45056 / (16*256) = exactly 11 iterations, no tail
    #pragma unroll 11
    for (int i = blockIdx.x * THREADS + threadIdx.x; i < SLICE4;
         i += BLOCKS_PER_SLICE * THREADS) {
        float4 x = a[i];
        float4 y = b[i];
        float d0 = x.x - y.x;
        float d1 = x.y - y.y;
        float d2 = x.z - y.z;
        float d3 = x.w - y.w;
        sum += d0 * d0 + d1 * d1 + d2 * d2 + d3 * d3;
    }

    // warp reduce
    #pragma unroll
    for (int o = 16; o > 0; o >>= 1)
        sum += __shfl_down_sync(0xffffffffu, sum, o);

    __shared__ float ws[THREADS / 32];
    if ((threadIdx.x & 31) == 0) ws[threadIdx.x >> 5] = sum;
    __syncthreads();

    if (threadIdx.x < (THREADS / 32)) {
        float v = ws[threadIdx.x];
        #pragma unroll
        for (int o = (THREADS / 64); o > 0; o >>= 1)
            v += __shfl_down_sync(0xffu, v, o);
        if (threadIdx.x == 0)
            g_partial[p * BLOCKS_PER_SLICE + blockIdx.x] = v;
    }
}

__global__ void finalize_kernel(const float* __restrict__ label_preds,
                                const float* __restrict__ labels,
                                float* __restrict__ out) {
    const int p = blockIdx.x;            // slice = s*B + b
    const int s = p / B_DIM;
    const int b = p % B_DIM;
    const int tid = threadIdx.x;

    // Label loss: 77 squared diffs, block-reduced
    float lsum = 0.0f;
    if (tid < LBL) {
        float d = label_preds[(size_t)p * LBL + tid] - labels[b * LBL + tid];
        lsum = d * d;
    }
    #pragma unroll
    for (int o = 16; o > 0; o >>= 1)
        lsum += __shfl_down_sync(0xffffffffu, lsum, o);

    __shared__ float ws[4];
    if ((tid & 31) == 0) ws[tid >> 5] = lsum;
    __syncthreads();

    if (tid == 0) {
        // labels_loss [B, S]
        out[NSLICE + b * S_DIM + s] = ws[0] + ws[1] + ws[2] + ws[3];

        // combined_loss [B, S]: fold the 16 heat partials, scale by 1/(H*W)
        float h = 0.0f;
        #pragma unroll
        for (int i = 0; i < BLOCKS_PER_SLICE; i++)
            h += g_partial[p * BLOCKS_PER_SLICE + i];
        out[b * S_DIM + s] = h * (1.0f / (float)(H_DIM * W_DIM));
    }
}

extern "C" void kernel_launch(void* const* d_in, const int* in_sizes, int n_in,
                              void* d_out, int out_size) {
    const float4* hp = (const float4*)d_in[0];   // heat_preds  [5,16,11,128,128]
    const float4* hm = (const float4*)d_in[1];   // heatmaps    [5,16,11,128,128]
    const float*  lp = (const float*)d_in[2];    // label_preds [5,16,11,7]
    const float*  lb = (const float*)d_in[3];    // labels      [16,11,7]
    float* out = (float*)d_out;                  // 160 floats: combined | labels_loss

    dim3 grid(BLOCKS_PER_SLICE, NSLICE);
    heat_partial_kernel<<<grid, THREADS>>>(hp, hm);
    finalize_kernel<<<NSLICE, 128>>>(lp, lb, out);
}